// round 5
// baseline (speedup 1.0000x reference)
#include <cuda_runtime.h>
#include <cuda_bf16.h>
#include <cstdint>

#define DI __device__ __forceinline__

static constexpr int BB   = 256;
static constexpr int HH   = 128;
static constexpr int GD   = 384;
static constexpr int NTREE= 1023;
static constexpr int KW   = 768;     // comb row: [hi(384) | lo(384)] bf16
static constexpr int KBIG = 1152;    // virtual K = 3 * 384 (split-bf16 3-pass)
static constexpr int NCH  = 18;      // K chunks of 64
static constexpr size_t RT = (size_t)BB * NTREE;   // 261888 rows over all levels

// ---------------- static device scratch ----------------
__device__ __nv_bfloat16 g_comb[RT * KW];             // 402MB, per-level regions
__device__ __nv_bfloat16 g_Wb[640 * KBIG];            // packed weights
__device__ float g_bpk[640];
__device__ float g_cst[2][(size_t)BB * 512 * HH];     // cell state ping-pong
__device__ float g_root[BB * HH];

// ---------------- helpers ----------------
DI uint32_t smem_u32(const void* p){ uint32_t a;
  asm("{ .reg .u64 t; cvta.to.shared.u64 t, %1; cvt.u32.u64 %0, t; }":"=r"(a):"l"(p)); return a; }
DI uint32_t swz(uint32_t o){ return o ^ ((o >> 3) & 0x70); }
DI void cp16(uint32_t dst, const void* src){
  asm volatile("cp.async.cg.shared.global [%0], [%1], 16;"
               ::"r"(dst),"l"(__cvta_generic_to_global(src)):"memory"); }
DI float sigf(float v){ return 1.f/(1.f+__expf(-v)); }
DI void ldsm4(uint32_t* a, uint32_t addr){
  asm volatile("ldmatrix.sync.aligned.m8n8.x4.shared.b16 {%0,%1,%2,%3}, [%4];"
    : "=r"(a[0]),"=r"(a[1]),"=r"(a[2]),"=r"(a[3]) : "r"(addr)); }
DI void hmma(float* d, const uint32_t* a, const uint32_t* b){
  asm volatile("mma.sync.aligned.m16n8k16.row.col.f32.bf16.bf16.f32 "
    "{%0,%1,%2,%3}, {%4,%5,%6,%7}, {%8,%9}, {%0,%1,%2,%3};"
    : "+f"(d[0]),"+f"(d[1]),"+f"(d[2]),"+f"(d[3])
    : "r"(a[0]),"r"(a[1]),"r"(a[2]),"r"(a[3]), "r"(b[0]),"r"(b[1])); }

// ---------------- pack weights ----------------
// packed n = (h>>3)*40 + g*8 + (h&7) ; K layout = [hi | hi | lo]
__global__ void pack_w(const float* __restrict__ Wi, const float* __restrict__ bi,
                       const float* __restrict__ Wfl,const float* __restrict__ bfl,
                       const float* __restrict__ Wfr,const float* __restrict__ bfr,
                       const float* __restrict__ Wo, const float* __restrict__ bo,
                       const float* __restrict__ Wu, const float* __restrict__ bu) {
    const float* Ws[5] = {Wi, Wfl, Wfr, Wo, Wu};
    const float* bs[5] = {bi, bfl, bfr, bo, bu};
    int idx = blockIdx.x * blockDim.x + threadIdx.x;
    if (idx < 640 * KBIG) {
        int nn = idx / KBIG, k = idx % KBIG;
        int p = k / GD, kp = k % GD;
        int hoct = nn / 40, rem = nn % 40, g = rem / 8, h3 = rem % 8;
        int h = hoct * 8 + h3;
        float w = Ws[g][h * GD + kp];
        __nv_bfloat16 hi = __float2bfloat16(w);
        g_Wb[idx] = (p < 2) ? hi : __float2bfloat16(w - __bfloat162float(hi));
    }
    if (idx < 640) {
        int hoct = idx / 40, rem = idx % 40, g = rem / 8, h3 = rem % 8;
        g_bpk[idx] = bs[g][hoct * 8 + h3];
    }
}

// ---------------- build x part of comb for ALL levels (one launch) ----------------
// level d occupies comb rows [256*(2^d-1), 256*(2^(d+1)-1))
__global__ void build_x_all(const float* __restrict__ x) {
    size_t idx = (size_t)blockIdx.x * blockDim.x + threadIdx.x;
    if (idx >= RT * 32) return;
    size_t rr = idx >> 5;
    int q = (int)(idx & 31);
    int d = 31 - __clz((int)(rr >> 8) + 1);
    int n = 1 << d;
    int r_in = (int)(rr - ((size_t)256 * (n - 1)));
    int b = r_in >> d, j = r_in & (n - 1);
    float4 v = reinterpret_cast<const float4*>(x)[((size_t)b * NTREE + (n - 1 + j)) * 32 + q];
    __nv_bfloat16 hb[4], lb[4];
    float vv[4] = {v.x, v.y, v.z, v.w};
    #pragma unroll
    for (int t = 0; t < 4; t++) {
        hb[t] = __float2bfloat16(vv[t]);
        lb[t] = __float2bfloat16(vv[t] - __bfloat162float(hb[t]));
    }
    __nv_bfloat16* row = g_comb + rr * KW;
    *reinterpret_cast<uint2*>(row + q * 4)       = *reinterpret_cast<uint2*>(hb);
    *reinterpret_cast<uint2*>(row + 384 + q * 4) = *reinterpret_cast<uint2*>(lb);
    if (d == 9) {   // leaves: zero children-h regions
        uint4 z = make_uint4(0, 0, 0, 0);
        *reinterpret_cast<uint4*>(row + 128 + q * 8) = z;
        *reinterpret_cast<uint4*>(row + 512 + q * 8) = z;
    }
}

// ---------------- fused GEMM (mma.sync bf16) + LSTM epilogue ----------------
// CTA: 128 rows x 320 packed cols (= 8 h-octets x 5 gates x 8 h), K = 1152
// 8 warps: warpM = wid>>2 (64 rows), warpN = wid&3 (80 cols = 2 hoct slices)
static constexpr uint32_t STAGE_A = 128 * 128;           // 16384
static constexpr uint32_t STAGE   = STAGE_A + 320 * 128; // 57344
static constexpr uint32_t SMEM_BYTES = 2048 + 2 * STAGE; // 116736

__global__ void __launch_bounds__(256, 1) gemm_fused(
    int n, int log2n, int parity, int parity_prev, int has_children, int is_root,
    size_t cur_off, size_t par_off)
{
    extern __shared__ char smem[];
    const uint32_t sb = smem_u32(smem);
    const int tid = threadIdx.x, wid = tid >> 5, lane = tid & 31;
    const int blkh = blockIdx.x;              // h half: packed n [blkh*320, +320)
    const int bm   = blockIdx.y * 128;
    const int warpM = wid >> 2, warpN = wid & 3;
    const __nv_bfloat16* comb_cur = g_comb + cur_off * KW;

    float* sbias = reinterpret_cast<float*>(smem);
    for (int t = tid; t < 320; t += 256)           // FIX: cover all 320 with 256 threads
        sbias[t] = g_bpk[blkh * 320 + t];

    float acc[4][10][4];
    #pragma unroll
    for (int a = 0; a < 4; a++)
      #pragma unroll
      for (int b = 0; b < 10; b++)
        #pragma unroll
        for (int c = 0; c < 4; c++) acc[a][b][c] = 0.f;

    auto load_chunk = [&](int ch) {
        const uint32_t base = sb + 2048 + (uint32_t)(ch & 1) * STAGE;
        const int p = ch / 6, kk = (ch % 6) * 64;
        const int acol = (p == 1) ? 384 + kk : kk;     // A' = [hi, lo, hi]
        const __nv_bfloat16* abase = comb_cur + (size_t)bm * KW + acol;
        #pragma unroll
        for (int l = 0; l < 4; l++) {
            int t = tid + l * 256; int row = t >> 3, c = t & 7;
            cp16(base + swz(row * 128 + c * 16),
                 reinterpret_cast<const char*>(abase + (size_t)row * KW) + c * 16);
        }
        const __nv_bfloat16* bbase = g_Wb + (size_t)(blkh * 320) * KBIG + ch * 64;
        #pragma unroll
        for (int l = 0; l < 10; l++) {
            int t = tid + l * 256; int row = t >> 3, c = t & 7;
            cp16(base + STAGE_A + swz(row * 128 + c * 16),
                 reinterpret_cast<const char*>(bbase + (size_t)row * KBIG) + c * 16);
        }
        asm volatile("cp.async.commit_group;" ::: "memory");
    };

    load_chunk(0); load_chunk(1);

    // ldmatrix lane addressing (shared by A and B tiles)
    const int mat = lane >> 3;
    const int lrow = (mat & 1) * 8 + (lane & 7);   // row within 16-row group
    const int lkb  = (mat >> 1) * 16;              // byte offset within k16 (0 or 16)
    const int a_row0 = warpM * 64 + lrow;
    const int b_row0 = warpN * 80 + lrow;

    for (int i = 0; i < NCH; i++) {
        if (i == NCH - 1) asm volatile("cp.async.wait_group 0;" ::: "memory");
        else              asm volatile("cp.async.wait_group 1;" ::: "memory");
        __syncthreads();
        const uint32_t base = sb + 2048 + (uint32_t)(i & 1) * STAGE;
        #pragma unroll
        for (int kk = 0; kk < 4; kk++) {
            // B frags: 5 ldsm.x4 over n16 groups -> 10 n8 frags
            uint32_t bf[10][2];
            #pragma unroll
            for (int s = 0; s < 5; s++) {
                uint32_t r[4];
                uint32_t o = (uint32_t)((b_row0 + s * 16) * 128 + kk * 32 + lkb);
                ldsm4(r, base + STAGE_A + swz(o));
                bf[s * 2][0] = r[0]; bf[s * 2][1] = r[2];
                bf[s * 2 + 1][0] = r[1]; bf[s * 2 + 1][1] = r[3];
            }
            #pragma unroll
            for (int mi = 0; mi < 4; mi++) {
                uint32_t a[4];
                uint32_t o = (uint32_t)((a_row0 + mi * 16) * 128 + kk * 32 + lkb);
                ldsm4(a, base + swz(o));
                #pragma unroll
                for (int j = 0; j < 10; j++) hmma(acc[mi][j], a, bf[j]);
            }
        }
        __syncthreads();
        if (i + 2 < NCH) load_chunk(i + 2);
    }

    // ---- fused epilogue: all 5 gates for (r,h) live in this thread ----
    const float* cprev = g_cst[parity_prev];
    float* cout = g_cst[parity];
    #pragma unroll
    for (int mi = 0; mi < 4; mi++) {
        #pragma unroll
        for (int j2 = 0; j2 < 2; j2++) {
            #pragma unroll
            for (int c = 0; c < 4; c++) {
                int r = bm + warpM * 64 + mi * 16 + (lane >> 2) + ((c & 2) ? 8 : 0);
                int hsub = (lane & 3) * 2 + (c & 1);
                int h = (blkh * 8 + warpN * 2 + j2) * 8 + hsub;
                int nl = warpN * 80 + j2 * 40;
                float vi  = sigf(acc[mi][j2*5+0][c] + sbias[nl +  0 + hsub]);
                float vfl = sigf(acc[mi][j2*5+1][c] + sbias[nl +  8 + hsub]);
                float vfr = sigf(acc[mi][j2*5+2][c] + sbias[nl + 16 + hsub]);
                float vo  = sigf(acc[mi][j2*5+3][c] + sbias[nl + 24 + hsub]);
                float vu  = tanhf(acc[mi][j2*5+4][c] + sbias[nl + 32 + hsub]);
                int b_ = r >> log2n, j_ = r & (n - 1);
                float cl = 0.f, cr = 0.f;
                if (has_children) {
                    size_t chL = ((size_t)b_ * (2 * n) + 2 * j_) * HH;
                    cl = cprev[chL + h];
                    cr = cprev[chL + HH + h];
                }
                float cc = vi * vu + vfl * cl + vfr * cr;
                float hh = vo * tanhf(cc);
                cout[(size_t)r * HH + h] = cc;
                if (is_root) {
                    g_root[r * HH + h] = hh;
                } else {
                    __nv_bfloat16 hi = __float2bfloat16(hh);
                    __nv_bfloat16 lo = __float2bfloat16(hh - __bfloat162float(hi));
                    __nv_bfloat16* pc = g_comb + (par_off + (size_t)b_ * (n >> 1) + (j_ >> 1)) * KW
                                        + 128 + (j_ & 1) * 128;
                    pc[h] = hi;
                    pc[384 + h] = lo;
                }
            }
        }
    }
}

// ---------------- final classifier ----------------
__global__ void cls_kernel(const float* __restrict__ Wc, const float* __restrict__ bc,
                           float* __restrict__ out) {
    int idx = blockIdx.x * blockDim.x + threadIdx.x;
    if (idx >= BB * 5) return;
    int b = idx / 5, cc = idx % 5;
    const float* hr = g_root + (size_t)b * HH;
    float s = bc[cc];
    #pragma unroll 4
    for (int h = 0; h < HH; h++) s += hr[h] * Wc[cc * HH + h];
    out[idx] = s;
}

// ---------------- launch ----------------
extern "C" void kernel_launch(void* const* d_in, const int* in_sizes, int n_in,
                              void* d_out, int out_size) {
    (void)in_sizes; (void)n_in; (void)out_size;
    const float* x = (const float*)d_in[0];

    cudaFuncSetAttribute(gemm_fused, cudaFuncAttributeMaxDynamicSharedMemorySize, SMEM_BYTES);

    pack_w<<<(640 * KBIG + 255) / 256, 256>>>(
        (const float*)d_in[1], (const float*)d_in[2],
        (const float*)d_in[3], (const float*)d_in[4],
        (const float*)d_in[5], (const float*)d_in[6],
        (const float*)d_in[7], (const float*)d_in[8],
        (const float*)d_in[9], (const float*)d_in[10]);

    build_x_all<<<(unsigned)((RT * 32 + 255) / 256), 256>>>(x);

    for (int d = 9; d >= 0; d--) {
        int n = 1 << d;
        int R = BB * n;
        size_t cur_off = (size_t)256 * (n - 1);
        size_t par_off = (d > 0) ? (size_t)256 * ((n >> 1) - 1) : 0;
        dim3 grid(2, R / 128);
        gemm_fused<<<grid, 256, SMEM_BYTES>>>(n, d, d & 1, (d + 1) & 1, d < 9, d == 0,
                                              cur_off, par_off);
    }

    cls_kernel<<<(BB * 5 + 127) / 128, 128>>>(
        (const float*)d_in[11], (const float*)d_in[12], (float*)d_out);
}

// round 6
// speedup vs baseline: 1.1010x; 1.1010x over previous
#include <cuda_runtime.h>
#include <cuda_bf16.h>
#include <cstdint>

#define DI __device__ __forceinline__

static constexpr int BB   = 256;
static constexpr int HH   = 128;
static constexpr int GD   = 384;
static constexpr int NTREE= 1023;
static constexpr int KW   = 768;     // comb row: [hi(384) | lo(384)] bf16
static constexpr int KBIG = 1152;    // virtual K = 3 * 384 (split-bf16 3-pass)
static constexpr int NCH  = 18;      // K chunks of 64
static constexpr size_t RT = (size_t)BB * NTREE;   // 261888 rows over all levels

// ---------------- static device scratch ----------------
__device__ __nv_bfloat16 g_comb[RT * KW];             // 402MB, per-level regions
__device__ __nv_bfloat16 g_Wb[640 * KBIG];            // packed weights
__device__ float g_bpk[640];
__device__ float g_cst[2][(size_t)BB * 512 * HH];     // cell state ping-pong
__device__ float g_root[BB * HH];

// ---------------- helpers ----------------
DI uint32_t smem_u32(const void* p){ uint32_t a;
  asm("{ .reg .u64 t; cvta.to.shared.u64 t, %1; cvt.u32.u64 %0, t; }":"=r"(a):"l"(p)); return a; }
DI uint32_t swz(uint32_t o){ return o ^ ((o >> 3) & 0x70); }
DI void cp16(uint32_t dst, const void* src){
  asm volatile("cp.async.cg.shared.global [%0], [%1], 16;"
               ::"r"(dst),"l"(__cvta_generic_to_global(src)):"memory"); }
DI float sigf(float v){ return 1.f/(1.f+__expf(-v)); }
DI void ldsm4(uint32_t* a, uint32_t addr){
  asm volatile("ldmatrix.sync.aligned.m8n8.x4.shared.b16 {%0,%1,%2,%3}, [%4];"
    : "=r"(a[0]),"=r"(a[1]),"=r"(a[2]),"=r"(a[3]) : "r"(addr)); }
DI void ldsm2(uint32_t* a, uint32_t addr){
  asm volatile("ldmatrix.sync.aligned.m8n8.x2.shared.b16 {%0,%1}, [%2];"
    : "=r"(a[0]),"=r"(a[1]) : "r"(addr)); }
DI void hmma(float* d, const uint32_t* a, const uint32_t* b){
  asm volatile("mma.sync.aligned.m16n8k16.row.col.f32.bf16.bf16.f32 "
    "{%0,%1,%2,%3}, {%4,%5,%6,%7}, {%8,%9}, {%0,%1,%2,%3};"
    : "+f"(d[0]),"+f"(d[1]),"+f"(d[2]),"+f"(d[3])
    : "r"(a[0]),"r"(a[1]),"r"(a[2]),"r"(a[3]), "r"(b[0]),"r"(b[1])); }

// ---------------- pack weights ----------------
// packed n = (h>>3)*40 + g*8 + (h&7) ; K layout = [hi | hi | lo]
__global__ void pack_w(const float* __restrict__ Wi, const float* __restrict__ bi,
                       const float* __restrict__ Wfl,const float* __restrict__ bfl,
                       const float* __restrict__ Wfr,const float* __restrict__ bfr,
                       const float* __restrict__ Wo, const float* __restrict__ bo,
                       const float* __restrict__ Wu, const float* __restrict__ bu) {
    const float* Ws[5] = {Wi, Wfl, Wfr, Wo, Wu};
    const float* bs[5] = {bi, bfl, bfr, bo, bu};
    int idx = blockIdx.x * blockDim.x + threadIdx.x;
    if (idx < 640 * KBIG) {
        int nn = idx / KBIG, k = idx % KBIG;
        int p = k / GD, kp = k % GD;
        int hoct = nn / 40, rem = nn % 40, g = rem / 8, h3 = rem % 8;
        int h = hoct * 8 + h3;
        float w = Ws[g][h * GD + kp];
        __nv_bfloat16 hi = __float2bfloat16(w);
        g_Wb[idx] = (p < 2) ? hi : __float2bfloat16(w - __bfloat162float(hi));
    }
    if (idx < 640) {
        int hoct = idx / 40, rem = idx % 40, g = rem / 8, h3 = rem % 8;
        g_bpk[idx] = bs[g][hoct * 8 + h3];
    }
}

// ---------------- build x part of comb for ALL levels (one launch) ----------------
__global__ void build_x_all(const float* __restrict__ x) {
    size_t idx = (size_t)blockIdx.x * blockDim.x + threadIdx.x;
    if (idx >= RT * 32) return;
    size_t rr = idx >> 5;
    int q = (int)(idx & 31);
    int d = 31 - __clz((int)(rr >> 8) + 1);
    int n = 1 << d;
    int r_in = (int)(rr - ((size_t)256 * (n - 1)));
    int b = r_in >> d, j = r_in & (n - 1);
    float4 v = reinterpret_cast<const float4*>(x)[((size_t)b * NTREE + (n - 1 + j)) * 32 + q];
    __nv_bfloat16 hb[4], lb[4];
    float vv[4] = {v.x, v.y, v.z, v.w};
    #pragma unroll
    for (int t = 0; t < 4; t++) {
        hb[t] = __float2bfloat16(vv[t]);
        lb[t] = __float2bfloat16(vv[t] - __bfloat162float(hb[t]));
    }
    __nv_bfloat16* row = g_comb + rr * KW;
    *reinterpret_cast<uint2*>(row + q * 4)       = *reinterpret_cast<uint2*>(hb);
    *reinterpret_cast<uint2*>(row + 384 + q * 4) = *reinterpret_cast<uint2*>(lb);
    if (d == 9) {
        uint4 z = make_uint4(0, 0, 0, 0);
        *reinterpret_cast<uint4*>(row + 128 + q * 8) = z;
        *reinterpret_cast<uint4*>(row + 512 + q * 8) = z;
    }
}

// ---------------- fused GEMM (mma.sync bf16) + LSTM epilogue ----------------
// CTA: 128 rows x 320 packed cols, 512 threads, 16 warps:
//   warpM = wid>>3 (64 rows), warpN = wid&7 (40 cols = 5 gates x 8 h)
// acc per thread = 80 fp32 -> fits 128-reg budget, no spills.
static constexpr uint32_t STAGE_A = 128 * 128;           // 16384
static constexpr uint32_t STAGE   = STAGE_A + 320 * 128; // 57344
static constexpr int NSTAGE = 3;
static constexpr uint32_t SMEM_BYTES = 2048 + NSTAGE * STAGE; // 174080

__global__ void __launch_bounds__(512, 1) gemm_fused(
    int n, int log2n, int parity, int parity_prev, int has_children, int is_root,
    size_t cur_off, size_t par_off)
{
    extern __shared__ char smem[];
    const uint32_t sb = smem_u32(smem);
    const int tid = threadIdx.x, wid = tid >> 5, lane = tid & 31;
    const int blkh = blockIdx.x;              // packed n [blkh*320, +320)
    const int bm   = blockIdx.y * 128;
    const int warpM = wid >> 3, warpN = wid & 7;
    const __nv_bfloat16* comb_cur = g_comb + cur_off * KW;

    float* sbias = reinterpret_cast<float*>(smem);
    for (int t = tid; t < 320; t += 512)
        sbias[t] = g_bpk[blkh * 320 + t];

    float acc[4][5][4];
    #pragma unroll
    for (int a = 0; a < 4; a++)
      #pragma unroll
      for (int b = 0; b < 5; b++)
        #pragma unroll
        for (int c = 0; c < 4; c++) acc[a][b][c] = 0.f;

    auto load_chunk = [&](int ch) {
        const uint32_t base = sb + 2048 + (uint32_t)(ch % NSTAGE) * STAGE;
        const int p = ch / 6, kk = (ch % 6) * 64;
        const int acol = (p == 1) ? 384 + kk : kk;     // A' = [hi, lo, hi]
        const __nv_bfloat16* abase = comb_cur + (size_t)bm * KW + acol;
        #pragma unroll
        for (int l = 0; l < 2; l++) {                  // A: 128 rows x 8 xf4
            int t = tid + l * 512; int row = t >> 3, c = t & 7;
            cp16(base + swz(row * 128 + c * 16),
                 reinterpret_cast<const char*>(abase + (size_t)row * KW) + c * 16);
        }
        const __nv_bfloat16* bbase = g_Wb + (size_t)(blkh * 320) * KBIG + ch * 64;
        #pragma unroll
        for (int l = 0; l < 5; l++) {                  // B: 320 rows x 8 xf4
            int t = tid + l * 512; int row = t >> 3, c = t & 7;
            cp16(base + STAGE_A + swz(row * 128 + c * 16),
                 reinterpret_cast<const char*>(bbase + (size_t)row * KBIG) + c * 16);
        }
        asm volatile("cp.async.commit_group;" ::: "memory");
    };

    load_chunk(0); load_chunk(1);

    // ldmatrix lane addressing
    const int mat = lane >> 3;
    const int lrow = (mat & 1) * 8 + (lane & 7);   // row within 16-row group (x4)
    const int lkb  = (mat >> 1) * 16;              // k-byte half (x4)
    const int a_row0 = warpM * 64 + lrow;
    const int b_row0 = warpN * 40 + lrow;
    const int b2row  = warpN * 40 + 32 + (lane & 7);        // x2: rows 32..39
    const int b2kb   = ((lane >> 3) & 1) * 16;              // x2: k-byte half

    for (int i = 0; i < NCH; i++) {
        if (i == NCH - 1) asm volatile("cp.async.wait_group 0;" ::: "memory");
        else              asm volatile("cp.async.wait_group 1;" ::: "memory");
        __syncthreads();                       // chunk i visible; stage (i+2)%3 free
        if (i + 2 < NCH) load_chunk(i + 2);
        const uint32_t base = sb + 2048 + (uint32_t)(i % NSTAGE) * STAGE;
        #pragma unroll
        for (int kk = 0; kk < 4; kk++) {
            uint32_t bf[5][2];
            #pragma unroll
            for (int s = 0; s < 2; s++) {      // n8 groups 0..3 via 2x ldsm.x4
                uint32_t r[4];
                uint32_t o = (uint32_t)((b_row0 + s * 16) * 128 + kk * 32 + lkb);
                ldsm4(r, base + STAGE_A + swz(o));
                bf[s * 2][0] = r[0]; bf[s * 2][1] = r[2];
                bf[s * 2 + 1][0] = r[1]; bf[s * 2 + 1][1] = r[3];
            }
            {                                   // n8 group 4 via ldsm.x2
                uint32_t o2 = (uint32_t)(b2row * 128 + kk * 32 + b2kb);
                ldsm2(bf[4], base + STAGE_A + swz(o2));
            }
            #pragma unroll
            for (int mi = 0; mi < 4; mi++) {
                uint32_t a[4];
                uint32_t o = (uint32_t)((a_row0 + mi * 16) * 128 + kk * 32 + lkb);
                ldsm4(a, base + swz(o));
                #pragma unroll
                for (int j = 0; j < 5; j++) hmma(acc[mi][j], a, bf[j]);
            }
        }
    }

    // ---- fused epilogue: all 5 gates for (r,h) live in this thread ----
    const float* cprev = g_cst[parity_prev];
    float* cout = g_cst[parity];
    const int nl = warpN * 40;
    #pragma unroll
    for (int mi = 0; mi < 4; mi++) {
        #pragma unroll
        for (int c = 0; c < 4; c++) {
            int r = bm + warpM * 64 + mi * 16 + (lane >> 2) + ((c & 2) ? 8 : 0);
            int hsub = (lane & 3) * 2 + (c & 1);
            int h = (blkh * 8 + warpN) * 8 + hsub;
            float vi  = sigf(acc[mi][0][c] + sbias[nl +  0 + hsub]);
            float vfl = sigf(acc[mi][1][c] + sbias[nl +  8 + hsub]);
            float vfr = sigf(acc[mi][2][c] + sbias[nl + 16 + hsub]);
            float vo  = sigf(acc[mi][3][c] + sbias[nl + 24 + hsub]);
            float vu  = tanhf(acc[mi][4][c] + sbias[nl + 32 + hsub]);
            int b_ = r >> log2n, j_ = r & (n - 1);
            float cl = 0.f, cr = 0.f;
            if (has_children) {
                size_t chL = ((size_t)b_ * (2 * n) + 2 * j_) * HH;
                cl = cprev[chL + h];
                cr = cprev[chL + HH + h];
            }
            float cc = vi * vu + vfl * cl + vfr * cr;
            float hh = vo * tanhf(cc);
            cout[(size_t)r * HH + h] = cc;
            if (is_root) {
                g_root[r * HH + h] = hh;
            } else {
                __nv_bfloat16 hi = __float2bfloat16(hh);
                __nv_bfloat16 lo = __float2bfloat16(hh - __bfloat162float(hi));
                __nv_bfloat16* pc = g_comb + (par_off + (size_t)b_ * (n >> 1) + (j_ >> 1)) * KW
                                    + 128 + (j_ & 1) * 128;
                pc[h] = hi;
                pc[384 + h] = lo;
            }
        }
    }
}

// ---------------- final classifier ----------------
__global__ void cls_kernel(const float* __restrict__ Wc, const float* __restrict__ bc,
                           float* __restrict__ out) {
    int idx = blockIdx.x * blockDim.x + threadIdx.x;
    if (idx >= BB * 5) return;
    int b = idx / 5, cc = idx % 5;
    const float* hr = g_root + (size_t)b * HH;
    float s = bc[cc];
    #pragma unroll 4
    for (int h = 0; h < HH; h++) s += hr[h] * Wc[cc * HH + h];
    out[idx] = s;
}

// ---------------- launch ----------------
extern "C" void kernel_launch(void* const* d_in, const int* in_sizes, int n_in,
                              void* d_out, int out_size) {
    (void)in_sizes; (void)n_in; (void)out_size;
    const float* x = (const float*)d_in[0];

    cudaFuncSetAttribute(gemm_fused, cudaFuncAttributeMaxDynamicSharedMemorySize, SMEM_BYTES);

    pack_w<<<(640 * KBIG + 255) / 256, 256>>>(
        (const float*)d_in[1], (const float*)d_in[2],
        (const float*)d_in[3], (const float*)d_in[4],
        (const float*)d_in[5], (const float*)d_in[6],
        (const float*)d_in[7], (const float*)d_in[8],
        (const float*)d_in[9], (const float*)d_in[10]);

    build_x_all<<<(unsigned)((RT * 32 + 255) / 256), 256>>>(x);

    for (int d = 9; d >= 0; d--) {
        int n = 1 << d;
        int R = BB * n;
        size_t cur_off = (size_t)256 * (n - 1);
        size_t par_off = (d > 0) ? (size_t)256 * ((n >> 1) - 1) : 0;
        dim3 grid(2, R / 128);
        gemm_fused<<<grid, 512, SMEM_BYTES>>>(n, d, d & 1, (d + 1) & 1, d < 9, d == 0,
                                              cur_off, par_off);
    }

    cls_kernel<<<(BB * 5 + 127) / 128, 128>>>(
        (const float*)d_in[11], (const float*)d_in[12], (float*)d_out);
}

// round 7
// speedup vs baseline: 1.4430x; 1.3106x over previous
#include <cuda_runtime.h>
#include <cuda_fp16.h>
#include <cstdint>

#define DI __device__ __forceinline__

static constexpr int BB   = 256;
static constexpr int HH   = 128;
static constexpr int GD   = 384;
static constexpr int NTREE= 1023;
static constexpr int KW   = 768;     // comb row: [hi(384) | lo(384)] fp16
static constexpr int NCH  = 12;      // K chunks of 64: 2 passes x 6
static constexpr size_t RT = (size_t)BB * NTREE;   // 261888 rows over all levels

// ---------------- static device scratch ----------------
__device__ __half g_comb[RT * KW];                    // 402MB, per-level regions
__device__ __half g_Wb[640 * GD];                     // packed weights (hi only)
__device__ float g_bpk[640];
__device__ float g_cst[2][(size_t)BB * 512 * HH];     // cell state ping-pong
__device__ float g_root[BB * HH];

// ---------------- helpers ----------------
DI uint32_t smem_u32(const void* p){ uint32_t a;
  asm("{ .reg .u64 t; cvta.to.shared.u64 t, %1; cvt.u32.u64 %0, t; }":"=r"(a):"l"(p)); return a; }
DI uint32_t swz(uint32_t o){ return o ^ ((o >> 3) & 0x70); }
DI void cp16(uint32_t dst, const void* src){
  asm volatile("cp.async.cg.shared.global [%0], [%1], 16;"
               ::"r"(dst),"l"(__cvta_generic_to_global(src)):"memory"); }
DI float sigf(float v){ return 1.f/(1.f+__expf(-v)); }
DI void ldsm4(uint32_t* a, uint32_t addr){
  asm volatile("ldmatrix.sync.aligned.m8n8.x4.shared.b16 {%0,%1,%2,%3}, [%4];"
    : "=r"(a[0]),"=r"(a[1]),"=r"(a[2]),"=r"(a[3]) : "r"(addr)); }
DI void ldsm2(uint32_t* a, uint32_t addr){
  asm volatile("ldmatrix.sync.aligned.m8n8.x2.shared.b16 {%0,%1}, [%2];"
    : "=r"(a[0]),"=r"(a[1]) : "r"(addr)); }
DI void hmma(float* d, const uint32_t* a, const uint32_t* b){
  asm volatile("mma.sync.aligned.m16n8k16.row.col.f32.f16.f16.f32 "
    "{%0,%1,%2,%3}, {%4,%5,%6,%7}, {%8,%9}, {%0,%1,%2,%3};"
    : "+f"(d[0]),"+f"(d[1]),"+f"(d[2]),"+f"(d[3])
    : "r"(a[0]),"r"(a[1]),"r"(a[2]),"r"(a[3]), "r"(b[0]),"r"(b[1])); }

// ---------------- pack weights ----------------
// packed n = (h>>3)*40 + g*8 + (h&7) ; fp16 hi only
__global__ void pack_w(const float* __restrict__ Wi, const float* __restrict__ bi,
                       const float* __restrict__ Wfl,const float* __restrict__ bfl,
                       const float* __restrict__ Wfr,const float* __restrict__ bfr,
                       const float* __restrict__ Wo, const float* __restrict__ bo,
                       const float* __restrict__ Wu, const float* __restrict__ bu) {
    const float* Ws[5] = {Wi, Wfl, Wfr, Wo, Wu};
    const float* bs[5] = {bi, bfl, bfr, bo, bu};
    int idx = blockIdx.x * blockDim.x + threadIdx.x;
    if (idx < 640 * GD) {
        int nn = idx / GD, k = idx % GD;
        int hoct = nn / 40, rem = nn % 40, g = rem / 8, h3 = rem % 8;
        int h = hoct * 8 + h3;
        g_Wb[idx] = __float2half(Ws[g][h * GD + k]);
    }
    if (idx < 640) {
        int hoct = idx / 40, rem = idx % 40, g = rem / 8, h3 = rem % 8;
        g_bpk[idx] = bs[g][hoct * 8 + h3];
    }
}

// ---------------- build x part of comb for ALL levels (one launch) ----------------
__global__ void build_x_all(const float* __restrict__ x) {
    size_t idx = (size_t)blockIdx.x * blockDim.x + threadIdx.x;
    if (idx >= RT * 32) return;
    size_t rr = idx >> 5;
    int q = (int)(idx & 31);
    int d = 31 - __clz((int)(rr >> 8) + 1);
    int n = 1 << d;
    int r_in = (int)(rr - ((size_t)256 * (n - 1)));
    int b = r_in >> d, j = r_in & (n - 1);
    float4 v = reinterpret_cast<const float4*>(x)[((size_t)b * NTREE + (n - 1 + j)) * 32 + q];
    __half hb[4], lb[4];
    float vv[4] = {v.x, v.y, v.z, v.w};
    #pragma unroll
    for (int t = 0; t < 4; t++) {
        hb[t] = __float2half(vv[t]);
        lb[t] = __float2half(vv[t] - __half2float(hb[t]));
    }
    __half* row = g_comb + rr * KW;
    *reinterpret_cast<uint2*>(row + q * 4)       = *reinterpret_cast<uint2*>(hb);
    *reinterpret_cast<uint2*>(row + 384 + q * 4) = *reinterpret_cast<uint2*>(lb);
    if (d == 9) {
        uint4 z = make_uint4(0, 0, 0, 0);
        *reinterpret_cast<uint4*>(row + 128 + q * 8) = z;
        *reinterpret_cast<uint4*>(row + 512 + q * 8) = z;
    }
}

// ---------------- fused GEMM (mma.sync fp16, 2-pass split) + LSTM epilogue ----------------
// CTA: 128 rows x 320 packed cols, 512 threads, 16 warps:
//   warpM = wid>>3 (64 rows), warpN = wid&7 (40 cols = 5 gates x 8 h)
static constexpr uint32_t STAGE_A = 128 * 128;           // 16384
static constexpr uint32_t STAGE   = STAGE_A + 320 * 128; // 57344
static constexpr int NSTAGE = 3;
static constexpr uint32_t SMEM_BYTES = 2048 + NSTAGE * STAGE; // 174080

__global__ void __launch_bounds__(512, 1) gemm_fused(
    int n, int log2n, int parity, int parity_prev, int has_children, int is_root,
    size_t cur_off, size_t par_off)
{
    extern __shared__ char smem[];
    const uint32_t sb = smem_u32(smem);
    const int tid = threadIdx.x, wid = tid >> 5, lane = tid & 31;
    const int blkh = blockIdx.x;              // packed n [blkh*320, +320)
    const int bm   = blockIdx.y * 128;
    const int warpM = wid >> 3, warpN = wid & 7;
    const __half* comb_cur = g_comb + cur_off * KW;

    float* sbias = reinterpret_cast<float*>(smem);
    for (int t = tid; t < 320; t += 512)
        sbias[t] = g_bpk[blkh * 320 + t];

    float acc[4][5][4];
    #pragma unroll
    for (int a = 0; a < 4; a++)
      #pragma unroll
      for (int b = 0; b < 5; b++)
        #pragma unroll
        for (int c = 0; c < 4; c++) acc[a][b][c] = 0.f;

    auto load_chunk = [&](int ch) {
        const uint32_t base = sb + 2048 + (uint32_t)(ch % NSTAGE) * STAGE;
        const int p = ch / 6, kk = (ch % 6) * 64;
        const int acol = p ? 384 + kk : kk;            // A' = [hi | lo]
        const __half* abase = comb_cur + (size_t)bm * KW + acol;
        #pragma unroll
        for (int l = 0; l < 2; l++) {                  // A: 128 rows x 8 xf4
            int t = tid + l * 512; int row = t >> 3, c = t & 7;
            cp16(base + swz(row * 128 + c * 16),
                 reinterpret_cast<const char*>(abase + (size_t)row * KW) + c * 16);
        }
        const __half* bbase = g_Wb + (size_t)(blkh * 320) * GD + kk;  // B' = [hi | hi]
        #pragma unroll
        for (int l = 0; l < 5; l++) {                  // B: 320 rows x 8 xf4
            int t = tid + l * 512; int row = t >> 3, c = t & 7;
            cp16(base + STAGE_A + swz(row * 128 + c * 16),
                 reinterpret_cast<const char*>(bbase + (size_t)row * GD) + c * 16);
        }
        asm volatile("cp.async.commit_group;" ::: "memory");
    };

    load_chunk(0); load_chunk(1);

    // ldmatrix lane addressing
    const int mat = lane >> 3;
    const int lrow = (mat & 1) * 8 + (lane & 7);   // row within 16-row group (x4)
    const int lkb  = (mat >> 1) * 16;              // k-byte half (x4)
    const int a_row0 = warpM * 64 + lrow;
    const int b_row0 = warpN * 40 + lrow;
    const int b2row  = warpN * 40 + 32 + (lane & 7);        // x2: rows 32..39
    const int b2kb   = ((lane >> 3) & 1) * 16;              // x2: k-byte half

    for (int i = 0; i < NCH; i++) {
        if (i == NCH - 1) asm volatile("cp.async.wait_group 0;" ::: "memory");
        else              asm volatile("cp.async.wait_group 1;" ::: "memory");
        __syncthreads();                       // chunk i visible; stage (i+2)%3 free
        if (i + 2 < NCH) load_chunk(i + 2);
        const uint32_t base = sb + 2048 + (uint32_t)(i % NSTAGE) * STAGE;
        #pragma unroll
        for (int kk = 0; kk < 4; kk++) {
            uint32_t bf[5][2];
            #pragma unroll
            for (int s = 0; s < 2; s++) {      // n8 groups 0..3 via 2x ldsm.x4
                uint32_t r[4];
                uint32_t o = (uint32_t)((b_row0 + s * 16) * 128 + kk * 32 + lkb);
                ldsm4(r, base + STAGE_A + swz(o));
                bf[s * 2][0] = r[0]; bf[s * 2][1] = r[2];
                bf[s * 2 + 1][0] = r[1]; bf[s * 2 + 1][1] = r[3];
            }
            {                                   // n8 group 4 via ldsm.x2
                uint32_t o2 = (uint32_t)(b2row * 128 + kk * 32 + b2kb);
                ldsm2(bf[4], base + STAGE_A + swz(o2));
            }
            #pragma unroll
            for (int mi = 0; mi < 4; mi++) {
                uint32_t a[4];
                uint32_t o = (uint32_t)((a_row0 + mi * 16) * 128 + kk * 32 + lkb);
                ldsm4(a, base + swz(o));
                #pragma unroll
                for (int j = 0; j < 5; j++) hmma(acc[mi][j], a, bf[j]);
            }
        }
    }

    // ---- fused epilogue: all 5 gates for (r,h) live in this thread ----
    const float* cprev = g_cst[parity_prev];
    float* cout = g_cst[parity];
    const int nl = warpN * 40;
    #pragma unroll
    for (int mi = 0; mi < 4; mi++) {
        #pragma unroll
        for (int c = 0; c < 4; c++) {
            int r = bm + warpM * 64 + mi * 16 + (lane >> 2) + ((c & 2) ? 8 : 0);
            int hsub = (lane & 3) * 2 + (c & 1);
            int h = (blkh * 8 + warpN) * 8 + hsub;
            float vi  = sigf(acc[mi][0][c] + sbias[nl +  0 + hsub]);
            float vfl = sigf(acc[mi][1][c] + sbias[nl +  8 + hsub]);
            float vfr = sigf(acc[mi][2][c] + sbias[nl + 16 + hsub]);
            float vo  = sigf(acc[mi][3][c] + sbias[nl + 24 + hsub]);
            float vu  = tanhf(acc[mi][4][c] + sbias[nl + 32 + hsub]);
            int b_ = r >> log2n, j_ = r & (n - 1);
            float cl = 0.f, cr = 0.f;
            if (has_children) {
                size_t chL = ((size_t)b_ * (2 * n) + 2 * j_) * HH;
                cl = cprev[chL + h];
                cr = cprev[chL + HH + h];
            }
            float cc = vi * vu + vfl * cl + vfr * cr;
            float hh = vo * tanhf(cc);
            cout[(size_t)r * HH + h] = cc;
            if (is_root) {
                g_root[r * HH + h] = hh;
            } else {
                __half hi = __float2half(hh);
                __half lo = __float2half(hh - __half2float(hi));
                __half* pc = g_comb + (par_off + (size_t)b_ * (n >> 1) + (j_ >> 1)) * KW
                             + 128 + (j_ & 1) * 128;
                pc[h] = hi;
                pc[384 + h] = lo;
            }
        }
    }
}

// ---------------- final classifier ----------------
__global__ void cls_kernel(const float* __restrict__ Wc, const float* __restrict__ bc,
                           float* __restrict__ out) {
    int idx = blockIdx.x * blockDim.x + threadIdx.x;
    if (idx >= BB * 5) return;
    int b = idx / 5, cc = idx % 5;
    const float* hr = g_root + (size_t)b * HH;
    float s = bc[cc];
    #pragma unroll 4
    for (int h = 0; h < HH; h++) s += hr[h] * Wc[cc * HH + h];
    out[idx] = s;
}

// ---------------- launch ----------------
extern "C" void kernel_launch(void* const* d_in, const int* in_sizes, int n_in,
                              void* d_out, int out_size) {
    (void)in_sizes; (void)n_in; (void)out_size;
    const float* x = (const float*)d_in[0];

    cudaFuncSetAttribute(gemm_fused, cudaFuncAttributeMaxDynamicSharedMemorySize, SMEM_BYTES);

    pack_w<<<(640 * GD + 255) / 256, 256>>>(
        (const float*)d_in[1], (const float*)d_in[2],
        (const float*)d_in[3], (const float*)d_in[4],
        (const float*)d_in[5], (const float*)d_in[6],
        (const float*)d_in[7], (const float*)d_in[8],
        (const float*)d_in[9], (const float*)d_in[10]);

    build_x_all<<<(unsigned)((RT * 32 + 255) / 256), 256>>>(x);

    for (int d = 9; d >= 0; d--) {
        int n = 1 << d;
        int R = BB * n;
        size_t cur_off = (size_t)256 * (n - 1);
        size_t par_off = (d > 0) ? (size_t)256 * ((n >> 1) - 1) : 0;
        dim3 grid(2, R / 128);
        gemm_fused<<<grid, 512, SMEM_BYTES>>>(n, d, d & 1, (d + 1) & 1, d < 9, d == 0,
                                              cur_off, par_off);
    }

    cls_kernel<<<(BB * 5 + 127) / 128, 128>>>(
        (const float*)d_in[11], (const float*)d_in[12], (float*)d_out);
}

// round 8
// speedup vs baseline: 1.4740x; 1.0215x over previous
#include <cuda_runtime.h>
#include <cuda_fp16.h>
#include <cstdint>

#define DI __device__ __forceinline__

static constexpr int BB   = 256;
static constexpr int HH   = 128;
static constexpr int GD   = 384;
static constexpr int NTREE= 1023;
static constexpr int KW   = 768;     // comb row: [hi(384) | lo(384)] fp16
static constexpr int NCH  = 12;      // K chunks of 64: 2 passes x 6
static constexpr size_t RT = (size_t)BB * NTREE;   // 261888 rows over all levels

// ---------------- static device scratch ----------------
__device__ __half g_comb[RT * KW];                    // 402MB, per-level regions
__device__ __half g_Wb[640 * GD];                     // packed weights (hi only)
__device__ float g_bpk[640];
__device__ float g_cst[2][(size_t)BB * 512 * HH];     // cell state ping-pong
__device__ float g_root[BB * HH];

// ---------------- helpers ----------------
DI uint32_t smem_u32(const void* p){ uint32_t a;
  asm("{ .reg .u64 t; cvta.to.shared.u64 t, %1; cvt.u32.u64 %0, t; }":"=r"(a):"l"(p)); return a; }
DI uint32_t swz(uint32_t o){ return o ^ ((o >> 3) & 0x70); }
DI void cp16(uint32_t dst, const void* src){
  asm volatile("cp.async.cg.shared.global [%0], [%1], 16;"
               ::"r"(dst),"l"(__cvta_generic_to_global(src)):"memory"); }
DI float sigf(float v){ return 1.f/(1.f+__expf(-v)); }
DI void ldsm4(uint32_t* a, uint32_t addr){
  asm volatile("ldmatrix.sync.aligned.m8n8.x4.shared.b16 {%0,%1,%2,%3}, [%4];"
    : "=r"(a[0]),"=r"(a[1]),"=r"(a[2]),"=r"(a[3]) : "r"(addr)); }
DI void ldsm2(uint32_t* a, uint32_t addr){
  asm volatile("ldmatrix.sync.aligned.m8n8.x2.shared.b16 {%0,%1}, [%2];"
    : "=r"(a[0]),"=r"(a[1]) : "r"(addr)); }
DI void hmma(float* d, const uint32_t* a, const uint32_t* b){
  asm volatile("mma.sync.aligned.m16n8k16.row.col.f32.f16.f16.f32 "
    "{%0,%1,%2,%3}, {%4,%5,%6,%7}, {%8,%9}, {%0,%1,%2,%3};"
    : "+f"(d[0]),"+f"(d[1]),"+f"(d[2]),"+f"(d[3])
    : "r"(a[0]),"r"(a[1]),"r"(a[2]),"r"(a[3]), "r"(b[0]),"r"(b[1])); }

// ---------------- pack weights ----------------
// packed n = (h>>3)*40 + g*8 + (h&7) ; fp16 hi only
__global__ void pack_w(const float* __restrict__ Wi, const float* __restrict__ bi,
                       const float* __restrict__ Wfl,const float* __restrict__ bfl,
                       const float* __restrict__ Wfr,const float* __restrict__ bfr,
                       const float* __restrict__ Wo, const float* __restrict__ bo,
                       const float* __restrict__ Wu, const float* __restrict__ bu) {
    const float* Ws[5] = {Wi, Wfl, Wfr, Wo, Wu};
    const float* bs[5] = {bi, bfl, bfr, bo, bu};
    int idx = blockIdx.x * blockDim.x + threadIdx.x;
    if (idx < 640 * GD) {
        int nn = idx / GD, k = idx % GD;
        int hoct = nn / 40, rem = nn % 40, g = rem / 8, h3 = rem % 8;
        int h = hoct * 8 + h3;
        g_Wb[idx] = __float2half(Ws[g][h * GD + k]);
    }
    if (idx < 640) {
        int hoct = idx / 40, rem = idx % 40, g = rem / 8, h3 = rem % 8;
        g_bpk[idx] = bs[g][hoct * 8 + h3];
    }
}

// ---------------- build x part of comb for ALL levels (one launch) ----------------
__global__ void build_x_all(const float* __restrict__ x) {
    size_t idx = (size_t)blockIdx.x * blockDim.x + threadIdx.x;
    if (idx >= RT * 32) return;
    size_t rr = idx >> 5;
    int q = (int)(idx & 31);
    int d = 31 - __clz((int)(rr >> 8) + 1);
    int n = 1 << d;
    int r_in = (int)(rr - ((size_t)256 * (n - 1)));
    int b = r_in >> d, j = r_in & (n - 1);
    float4 v = reinterpret_cast<const float4*>(x)[((size_t)b * NTREE + (n - 1 + j)) * 32 + q];
    __half hb[4], lb[4];
    float vv[4] = {v.x, v.y, v.z, v.w};
    #pragma unroll
    for (int t = 0; t < 4; t++) {
        hb[t] = __float2half(vv[t]);
        lb[t] = __float2half(vv[t] - __half2float(hb[t]));
    }
    __half* row = g_comb + rr * KW;
    *reinterpret_cast<uint2*>(row + q * 4)       = *reinterpret_cast<uint2*>(hb);
    *reinterpret_cast<uint2*>(row + 384 + q * 4) = *reinterpret_cast<uint2*>(lb);
    if (d == 9) {
        uint4 z = make_uint4(0, 0, 0, 0);
        *reinterpret_cast<uint4*>(row + 128 + q * 8) = z;
        *reinterpret_cast<uint4*>(row + 512 + q * 8) = z;
    }
}

// ---------------- fused GEMM (mma.sync fp16, 2-pass split) + LSTM epilogue ----------------
// CTA: 128 rows x 160 packed cols, 256 threads, 8 warps, 2 CTAs/SM:
//   warpM = wid>>2 (64 rows), warpN = wid&3 (40 cols = 5 gates x 8 h)
static constexpr uint32_t STAGE_A = 128 * 128;           // 16384
static constexpr uint32_t STAGE   = STAGE_A + 160 * 128; // 36864
static constexpr int NSTAGE = 3;
static constexpr uint32_t SMEM_BYTES = 2048 + NSTAGE * STAGE; // 112640

__global__ void __launch_bounds__(256, 2) gemm_fused(
    int n, int log2n, int parity, int parity_prev, int has_children, int is_root,
    size_t cur_off, size_t par_off)
{
    extern __shared__ char smem[];
    const uint32_t sb = smem_u32(smem);
    const int tid = threadIdx.x, wid = tid >> 5, lane = tid & 31;
    const int blkh = blockIdx.x;              // packed n [blkh*160, +160)
    const int bm   = blockIdx.y * 128;
    const int warpM = wid >> 2, warpN = wid & 3;
    const __half* comb_cur = g_comb + cur_off * KW;

    float* sbias = reinterpret_cast<float*>(smem);
    if (tid < 160) sbias[tid] = g_bpk[blkh * 160 + tid];

    float acc[4][5][4];
    #pragma unroll
    for (int a = 0; a < 4; a++)
      #pragma unroll
      for (int b = 0; b < 5; b++)
        #pragma unroll
        for (int c = 0; c < 4; c++) acc[a][b][c] = 0.f;

    auto load_chunk = [&](int ch) {
        const uint32_t base = sb + 2048 + (uint32_t)(ch % NSTAGE) * STAGE;
        const int p = ch / 6, kk = (ch % 6) * 64;
        const int acol = p ? 384 + kk : kk;            // A' = [hi | lo]
        const __half* abase = comb_cur + (size_t)bm * KW + acol;
        #pragma unroll
        for (int l = 0; l < 4; l++) {                  // A: 128 rows x 8 xf4
            int t = tid + l * 256; int row = t >> 3, c = t & 7;
            cp16(base + swz(row * 128 + c * 16),
                 reinterpret_cast<const char*>(abase + (size_t)row * KW) + c * 16);
        }
        const __half* bbase = g_Wb + (size_t)(blkh * 160) * GD + kk;  // B' = [hi | hi]
        #pragma unroll
        for (int l = 0; l < 5; l++) {                  // B: 160 rows x 8 xf4
            int t = tid + l * 256; int row = t >> 3, c = t & 7;
            cp16(base + STAGE_A + swz(row * 128 + c * 16),
                 reinterpret_cast<const char*>(bbase + (size_t)row * GD) + c * 16);
        }
        asm volatile("cp.async.commit_group;" ::: "memory");
    };

    load_chunk(0); load_chunk(1);

    // ldmatrix lane addressing
    const int mat = lane >> 3;
    const int lrow = (mat & 1) * 8 + (lane & 7);   // row within 16-row group (x4)
    const int lkb  = (mat >> 1) * 16;              // k-byte half (x4)
    const int a_row0 = warpM * 64 + lrow;
    const int b_row0 = warpN * 40 + lrow;
    const int b2row  = warpN * 40 + 32 + (lane & 7);        // x2: rows 32..39
    const int b2kb   = ((lane >> 3) & 1) * 16;              // x2: k-byte half

    for (int i = 0; i < NCH; i++) {
        if (i == NCH - 1) asm volatile("cp.async.wait_group 0;" ::: "memory");
        else              asm volatile("cp.async.wait_group 1;" ::: "memory");
        __syncthreads();                       // chunk i visible; stage (i+2)%3 free
        if (i + 2 < NCH) load_chunk(i + 2);
        const uint32_t base = sb + 2048 + (uint32_t)(i % NSTAGE) * STAGE;
        #pragma unroll
        for (int kk = 0; kk < 4; kk++) {
            uint32_t bf[5][2];
            #pragma unroll
            for (int s = 0; s < 2; s++) {      // n8 groups 0..3 via 2x ldsm.x4
                uint32_t r[4];
                uint32_t o = (uint32_t)((b_row0 + s * 16) * 128 + kk * 32 + lkb);
                ldsm4(r, base + STAGE_A + swz(o));
                bf[s * 2][0] = r[0]; bf[s * 2][1] = r[2];
                bf[s * 2 + 1][0] = r[1]; bf[s * 2 + 1][1] = r[3];
            }
            {                                   // n8 group 4 via ldsm.x2
                uint32_t o2 = (uint32_t)(b2row * 128 + kk * 32 + b2kb);
                ldsm2(bf[4], base + STAGE_A + swz(o2));
            }
            #pragma unroll
            for (int mi = 0; mi < 4; mi++) {
                uint32_t a[4];
                uint32_t o = (uint32_t)((a_row0 + mi * 16) * 128 + kk * 32 + lkb);
                ldsm4(a, base + swz(o));
                #pragma unroll
                for (int j = 0; j < 5; j++) hmma(acc[mi][j], a, bf[j]);
            }
        }
    }

    // ---- fused epilogue: all 5 gates for (r,h) live in this thread ----
    const float* cprev = g_cst[parity_prev];
    float* cout = g_cst[parity];
    const int nl = warpN * 40;
    #pragma unroll
    for (int mi = 0; mi < 4; mi++) {
        #pragma unroll
        for (int c = 0; c < 4; c++) {
            int r = bm + warpM * 64 + mi * 16 + (lane >> 2) + ((c & 2) ? 8 : 0);
            int hsub = (lane & 3) * 2 + (c & 1);
            int h = (blkh * 4 + warpN) * 8 + hsub;
            float vi  = sigf(acc[mi][0][c] + sbias[nl +  0 + hsub]);
            float vfl = sigf(acc[mi][1][c] + sbias[nl +  8 + hsub]);
            float vfr = sigf(acc[mi][2][c] + sbias[nl + 16 + hsub]);
            float vo  = sigf(acc[mi][3][c] + sbias[nl + 24 + hsub]);
            float vu  = tanhf(acc[mi][4][c] + sbias[nl + 32 + hsub]);
            int b_ = r >> log2n, j_ = r & (n - 1);
            float cl = 0.f, cr = 0.f;
            if (has_children) {
                size_t chL = ((size_t)b_ * (2 * n) + 2 * j_) * HH;
                cl = cprev[chL + h];
                cr = cprev[chL + HH + h];
            }
            float cc = vi * vu + vfl * cl + vfr * cr;
            float hh = vo * tanhf(cc);
            cout[(size_t)r * HH + h] = cc;
            if (is_root) {
                g_root[r * HH + h] = hh;
            } else {
                __half hi = __float2half(hh);
                __half lo = __float2half(hh - __half2float(hi));
                __half* pc = g_comb + (par_off + (size_t)b_ * (n >> 1) + (j_ >> 1)) * KW
                             + 128 + (j_ & 1) * 128;
                pc[h] = hi;
                pc[384 + h] = lo;
            }
        }
    }
}

// ---------------- final classifier ----------------
__global__ void cls_kernel(const float* __restrict__ Wc, const float* __restrict__ bc,
                           float* __restrict__ out) {
    int idx = blockIdx.x * blockDim.x + threadIdx.x;
    if (idx >= BB * 5) return;
    int b = idx / 5, cc = idx % 5;
    const float* hr = g_root + (size_t)b * HH;
    float s = bc[cc];
    #pragma unroll 4
    for (int h = 0; h < HH; h++) s += hr[h] * Wc[cc * HH + h];
    out[idx] = s;
}

// ---------------- launch ----------------
extern "C" void kernel_launch(void* const* d_in, const int* in_sizes, int n_in,
                              void* d_out, int out_size) {
    (void)in_sizes; (void)n_in; (void)out_size;
    const float* x = (const float*)d_in[0];

    cudaFuncSetAttribute(gemm_fused, cudaFuncAttributeMaxDynamicSharedMemorySize, SMEM_BYTES);

    pack_w<<<(640 * GD + 255) / 256, 256>>>(
        (const float*)d_in[1], (const float*)d_in[2],
        (const float*)d_in[3], (const float*)d_in[4],
        (const float*)d_in[5], (const float*)d_in[6],
        (const float*)d_in[7], (const float*)d_in[8],
        (const float*)d_in[9], (const float*)d_in[10]);

    build_x_all<<<(unsigned)((RT * 32 + 255) / 256), 256>>>(x);

    for (int d = 9; d >= 0; d--) {
        int n = 1 << d;
        int R = BB * n;
        size_t cur_off = (size_t)256 * (n - 1);
        size_t par_off = (d > 0) ? (size_t)256 * ((n >> 1) - 1) : 0;
        dim3 grid(4, R / 128);
        gemm_fused<<<grid, 256, SMEM_BYTES>>>(n, d, d & 1, (d + 1) & 1, d < 9, d == 0,
                                              cur_off, par_off);
    }

    cls_kernel<<<(BB * 5 + 127) / 128, 128>>>(
        (const float*)d_in[11], (const float*)d_in[12], (float*)d_out);
}

// round 9
// speedup vs baseline: 1.8541x; 1.2579x over previous
#include <cuda_runtime.h>
#include <cuda_fp16.h>
#include <cstdint>

#define DI __device__ __forceinline__

static constexpr int BB   = 256;
static constexpr int HH   = 128;
static constexpr int GD   = 384;
static constexpr int NTREE= 1023;
static constexpr int KW   = 768;     // comb row: [hi(384) | lo(384)] fp16
static constexpr int NCH  = 12;      // K chunks of 64: 2 passes x 6
static constexpr size_t RT = (size_t)BB * NTREE;   // 261888 rows over all levels

// ---------------- static device scratch ----------------
__device__ __half g_comb[RT * KW];                    // 402MB, per-level regions
__device__ __half g_Wb[640 * GD];                     // packed weights (hi only)
__device__ float g_bpk[640];
__device__ float g_cst[2][(size_t)BB * 512 * HH];     // cell state ping-pong
__device__ float g_root[BB * HH];

// ---------------- helpers ----------------
DI uint32_t smem_u32(const void* p){ uint32_t a;
  asm("{ .reg .u64 t; cvta.to.shared.u64 t, %1; cvt.u32.u64 %0, t; }":"=r"(a):"l"(p)); return a; }
DI uint32_t swz(uint32_t o){ return o ^ ((o >> 3) & 0x70); }
DI void cp16(uint32_t dst, const void* src){
  asm volatile("cp.async.cg.shared.global [%0], [%1], 16;"
               ::"r"(dst),"l"(__cvta_generic_to_global(src)):"memory"); }
DI float sigf(float v){ return 1.f/(1.f+__expf(-v)); }
DI void ldsm4(uint32_t* a, uint32_t addr){
  asm volatile("ldmatrix.sync.aligned.m8n8.x4.shared.b16 {%0,%1,%2,%3}, [%4];"
    : "=r"(a[0]),"=r"(a[1]),"=r"(a[2]),"=r"(a[3]) : "r"(addr)); }
DI void ldsm2(uint32_t* a, uint32_t addr){
  asm volatile("ldmatrix.sync.aligned.m8n8.x2.shared.b16 {%0,%1}, [%2];"
    : "=r"(a[0]),"=r"(a[1]) : "r"(addr)); }
DI void hmma(float* d, const uint32_t* a, const uint32_t* b){
  asm volatile("mma.sync.aligned.m16n8k16.row.col.f32.f16.f16.f32 "
    "{%0,%1,%2,%3}, {%4,%5,%6,%7}, {%8,%9}, {%0,%1,%2,%3};"
    : "+f"(d[0]),"+f"(d[1]),"+f"(d[2]),"+f"(d[3])
    : "r"(a[0]),"r"(a[1]),"r"(a[2]),"r"(a[3]), "r"(b[0]),"r"(b[1])); }

// ---------------- pack weights ----------------
// packed n = (h>>3)*40 + g*8 + (h&7) ; fp16 hi only
__global__ void pack_w(const float* __restrict__ Wi, const float* __restrict__ bi,
                       const float* __restrict__ Wfl,const float* __restrict__ bfl,
                       const float* __restrict__ Wfr,const float* __restrict__ bfr,
                       const float* __restrict__ Wo, const float* __restrict__ bo,
                       const float* __restrict__ Wu, const float* __restrict__ bu) {
    const float* Ws[5] = {Wi, Wfl, Wfr, Wo, Wu};
    const float* bs[5] = {bi, bfl, bfr, bo, bu};
    int idx = blockIdx.x * blockDim.x + threadIdx.x;
    if (idx < 640 * GD) {
        int nn = idx / GD, k = idx % GD;
        int hoct = nn / 40, rem = nn % 40, g = rem / 8, h3 = rem % 8;
        int h = hoct * 8 + h3;
        g_Wb[idx] = __float2half(Ws[g][h * GD + k]);
    }
    if (idx < 640) {
        int hoct = idx / 40, rem = idx % 40, g = rem / 8, h3 = rem % 8;
        g_bpk[idx] = bs[g][hoct * 8 + h3];
    }
}

// ---------------- build x part of comb for ALL levels (one launch) ----------------
__global__ void build_x_all(const float* __restrict__ x) {
    size_t idx = (size_t)blockIdx.x * blockDim.x + threadIdx.x;
    if (idx >= RT * 32) return;
    size_t rr = idx >> 5;
    int q = (int)(idx & 31);
    int d = 31 - __clz((int)(rr >> 8) + 1);
    int n = 1 << d;
    int r_in = (int)(rr - ((size_t)256 * (n - 1)));
    int b = r_in >> d, j = r_in & (n - 1);
    float4 v = reinterpret_cast<const float4*>(x)[((size_t)b * NTREE + (n - 1 + j)) * 32 + q];
    __half hb[4], lb[4];
    float vv[4] = {v.x, v.y, v.z, v.w};
    #pragma unroll
    for (int t = 0; t < 4; t++) {
        hb[t] = __float2half(vv[t]);
        lb[t] = __float2half(vv[t] - __half2float(hb[t]));
    }
    __half* row = g_comb + rr * KW;
    *reinterpret_cast<uint2*>(row + q * 4)       = *reinterpret_cast<uint2*>(hb);
    *reinterpret_cast<uint2*>(row + 384 + q * 4) = *reinterpret_cast<uint2*>(lb);
    if (d == 9) {
        uint4 z = make_uint4(0, 0, 0, 0);
        *reinterpret_cast<uint4*>(row + 128 + q * 8) = z;
        *reinterpret_cast<uint4*>(row + 512 + q * 8) = z;
    }
}

// ---------------- fused GEMM (mma.sync fp16, 2-pass split) + LSTM epilogue ----------------
// CTA: 128 rows x 80 packed cols, 256 threads, 8 warps, 3 CTAs/SM (24 warps):
//   warpM = wid>>1 (32 rows), warpN = wid&1 (40 cols = 5 gates x 8 h)
// acc per thread = 40 fp32 -> ~84 regs total, no spills at launch_bounds(256,3).
static constexpr uint32_t STAGE_A = 128 * 128;           // 16384
static constexpr uint32_t STAGE   = STAGE_A + 80 * 128;  // 26624
static constexpr int NSTAGE = 2;
static constexpr uint32_t SMEM_BYTES = 2048 + NSTAGE * STAGE; // 55296 (x3 CTA = 166KB)

__global__ void __launch_bounds__(256, 3) gemm_fused(
    int n, int log2n, int parity, int parity_prev, int has_children, int is_root,
    size_t cur_off, size_t par_off)
{
    extern __shared__ char smem[];
    const uint32_t sb = smem_u32(smem);
    const int tid = threadIdx.x, wid = tid >> 5, lane = tid & 31;
    const int blkh = blockIdx.x;              // packed n [blkh*80, +80)
    const int bm   = blockIdx.y * 128;
    const int warpM = wid >> 1, warpN = wid & 1;
    const __half* comb_cur = g_comb + cur_off * KW;

    float* sbias = reinterpret_cast<float*>(smem);
    if (tid < 80) sbias[tid] = g_bpk[blkh * 80 + tid];

    float acc[2][5][4];
    #pragma unroll
    for (int a = 0; a < 2; a++)
      #pragma unroll
      for (int b = 0; b < 5; b++)
        #pragma unroll
        for (int c = 0; c < 4; c++) acc[a][b][c] = 0.f;

    auto load_chunk = [&](int ch) {
        const uint32_t base = sb + 2048 + (uint32_t)(ch & 1) * STAGE;
        const int p = ch / 6, kk = (ch % 6) * 64;
        const int acol = p ? 384 + kk : kk;            // A' = [hi | lo]
        const __half* abase = comb_cur + (size_t)bm * KW + acol;
        #pragma unroll
        for (int l = 0; l < 4; l++) {                  // A: 128 rows x 8 xf4
            int t = tid + l * 256; int row = t >> 3, c = t & 7;
            cp16(base + swz(row * 128 + c * 16),
                 reinterpret_cast<const char*>(abase + (size_t)row * KW) + c * 16);
        }
        const __half* bbase = g_Wb + (size_t)(blkh * 80) * GD + kk;  // B' = [hi | hi]
        #pragma unroll
        for (int l = 0; l < 3; l++) {                  // B: 80 rows x 8 xf4 = 640
            int t = tid + l * 256;
            if (t < 640) {
                int row = t >> 3, c = t & 7;
                cp16(base + STAGE_A + swz(row * 128 + c * 16),
                     reinterpret_cast<const char*>(bbase + (size_t)row * GD) + c * 16);
            }
        }
        asm volatile("cp.async.commit_group;" ::: "memory");
    };

    load_chunk(0);

    // ldmatrix lane addressing
    const int mat = lane >> 3;
    const int lrow = (mat & 1) * 8 + (lane & 7);   // row within 16-row group (x4)
    const int lkb  = (mat >> 1) * 16;              // k-byte half (x4)
    const int a_row0 = warpM * 32 + lrow;
    const int b_row0 = warpN * 40 + lrow;
    const int b2row  = warpN * 40 + 32 + (lane & 7);        // x2: rows 32..39
    const int b2kb   = ((lane >> 3) & 1) * 16;              // x2: k-byte half

    for (int i = 0; i < NCH; i++) {
        asm volatile("cp.async.wait_group 0;" ::: "memory");
        __syncthreads();                 // chunk i visible; all done with stage i&1 prev use
        if (i + 1 < NCH) load_chunk(i + 1);
        const uint32_t base = sb + 2048 + (uint32_t)(i & 1) * STAGE;
        #pragma unroll
        for (int kk = 0; kk < 4; kk++) {
            uint32_t bf[5][2];
            {                                   // n8 groups 0..3 via 2x ldsm.x4
                uint32_t r[4];
                uint32_t o = (uint32_t)(b_row0 * 128 + kk * 32 + lkb);
                ldsm4(r, base + STAGE_A + swz(o));
                bf[0][0] = r[0]; bf[0][1] = r[2];
                bf[1][0] = r[1]; bf[1][1] = r[3];
                uint32_t o1 = (uint32_t)((b_row0 + 16) * 128 + kk * 32 + lkb);
                ldsm4(r, base + STAGE_A + swz(o1));
                bf[2][0] = r[0]; bf[2][1] = r[2];
                bf[3][0] = r[1]; bf[3][1] = r[3];
                uint32_t o2 = (uint32_t)(b2row * 128 + kk * 32 + b2kb);
                ldsm2(bf[4], base + STAGE_A + swz(o2));
            }
            #pragma unroll
            for (int mi = 0; mi < 2; mi++) {
                uint32_t a[4];
                uint32_t o = (uint32_t)((a_row0 + mi * 16) * 128 + kk * 32 + lkb);
                ldsm4(a, base + swz(o));
                #pragma unroll
                for (int j = 0; j < 5; j++) hmma(acc[mi][j], a, bf[j]);
            }
        }
    }

    // ---- fused epilogue: all 5 gates for (r,h) live in this thread ----
    const float* cprev = g_cst[parity_prev];
    float* cout = g_cst[parity];
    const int nl = warpN * 40;
    #pragma unroll
    for (int mi = 0; mi < 2; mi++) {
        #pragma unroll
        for (int c = 0; c < 4; c++) {
            int r = bm + warpM * 32 + mi * 16 + (lane >> 2) + ((c & 2) ? 8 : 0);
            int hsub = (lane & 3) * 2 + (c & 1);
            int h = (blkh * 2 + warpN) * 8 + hsub;
            float vi  = sigf(acc[mi][0][c] + sbias[nl +  0 + hsub]);
            float vfl = sigf(acc[mi][1][c] + sbias[nl +  8 + hsub]);
            float vfr = sigf(acc[mi][2][c] + sbias[nl + 16 + hsub]);
            float vo  = sigf(acc[mi][3][c] + sbias[nl + 24 + hsub]);
            float vu  = tanhf(acc[mi][4][c] + sbias[nl + 32 + hsub]);
            int b_ = r >> log2n, j_ = r & (n - 1);
            float cl = 0.f, cr = 0.f;
            if (has_children) {
                size_t chL = ((size_t)b_ * (2 * n) + 2 * j_) * HH;
                cl = cprev[chL + h];
                cr = cprev[chL + HH + h];
            }
            float cc = vi * vu + vfl * cl + vfr * cr;
            float hh = vo * tanhf(cc);
            cout[(size_t)r * HH + h] = cc;
            if (is_root) {
                g_root[r * HH + h] = hh;
            } else {
                __half hi = __float2half(hh);
                __half lo = __float2half(hh - __half2float(hi));
                __half* pc = g_comb + (par_off + (size_t)b_ * (n >> 1) + (j_ >> 1)) * KW
                             + 128 + (j_ & 1) * 128;
                pc[h] = hi;
                pc[384 + h] = lo;
            }
        }
    }
}

// ---------------- final classifier ----------------
__global__ void cls_kernel(const float* __restrict__ Wc, const float* __restrict__ bc,
                           float* __restrict__ out) {
    int idx = blockIdx.x * blockDim.x + threadIdx.x;
    if (idx >= BB * 5) return;
    int b = idx / 5, cc = idx % 5;
    const float* hr = g_root + (size_t)b * HH;
    float s = bc[cc];
    #pragma unroll 4
    for (int h = 0; h < HH; h++) s += hr[h] * Wc[cc * HH + h];
    out[idx] = s;
}

// ---------------- launch ----------------
extern "C" void kernel_launch(void* const* d_in, const int* in_sizes, int n_in,
                              void* d_out, int out_size) {
    (void)in_sizes; (void)n_in; (void)out_size;
    const float* x = (const float*)d_in[0];

    cudaFuncSetAttribute(gemm_fused, cudaFuncAttributeMaxDynamicSharedMemorySize, SMEM_BYTES);

    pack_w<<<(640 * GD + 255) / 256, 256>>>(
        (const float*)d_in[1], (const float*)d_in[2],
        (const float*)d_in[3], (const float*)d_in[4],
        (const float*)d_in[5], (const float*)d_in[6],
        (const float*)d_in[7], (const float*)d_in[8],
        (const float*)d_in[9], (const float*)d_in[10]);

    build_x_all<<<(unsigned)((RT * 32 + 255) / 256), 256>>>(x);

    for (int d = 9; d >= 0; d--) {
        int n = 1 << d;
        int R = BB * n;
        size_t cur_off = (size_t)256 * (n - 1);
        size_t par_off = (d > 0) ? (size_t)256 * ((n >> 1) - 1) : 0;
        dim3 grid(8, R / 128);    // blkh fastest -> 8 CTAs sharing one A block co-resident (L2 reuse)
        gemm_fused<<<grid, 256, SMEM_BYTES>>>(n, d, d & 1, (d + 1) & 1, d < 9, d == 0,
                                              cur_off, par_off);
    }

    cls_kernel<<<(BB * 5 + 127) / 128, 128>>>(
        (const float*)d_in[11], (const float*)d_in[12], (float*)d_out);
}

// round 10
// speedup vs baseline: 2.7837x; 1.5013x over previous
#include <cuda_runtime.h>
#include <cuda_fp16.h>
#include <cstdint>

#define DI __device__ __forceinline__

static constexpr int BB   = 256;
static constexpr int HH   = 128;
static constexpr int GD   = 384;
static constexpr int NTREE= 1023;
static constexpr int KW   = 384;     // comb row: fp16 (single precision pass)
static constexpr int NCH  = 6;       // K chunks of 64
static constexpr size_t RT = (size_t)BB * NTREE;   // 261888 rows over all levels

// ---------------- static device scratch ----------------
__device__ __half g_comb[RT * KW];                    // 201MB, per-level regions
__device__ __half g_Wb[640 * GD];                     // packed weights
__device__ float g_bpk[640];
__device__ float g_cst[2][(size_t)BB * 512 * HH];     // cell state ping-pong
__device__ float g_root[BB * HH];

// ---------------- helpers ----------------
DI uint32_t smem_u32(const void* p){ uint32_t a;
  asm("{ .reg .u64 t; cvta.to.shared.u64 t, %1; cvt.u32.u64 %0, t; }":"=r"(a):"l"(p)); return a; }
DI uint32_t swz(uint32_t o){ return o ^ ((o >> 3) & 0x70); }
DI void cp16(uint32_t dst, const void* src){
  asm volatile("cp.async.cg.shared.global [%0], [%1], 16;"
               ::"r"(dst),"l"(__cvta_generic_to_global(src)):"memory"); }
DI float sigf(float v){ return 1.f/(1.f+__expf(-v)); }
DI void ldsm4(uint32_t* a, uint32_t addr){
  asm volatile("ldmatrix.sync.aligned.m8n8.x4.shared.b16 {%0,%1,%2,%3}, [%4];"
    : "=r"(a[0]),"=r"(a[1]),"=r"(a[2]),"=r"(a[3]) : "r"(addr)); }
DI void ldsm2(uint32_t* a, uint32_t addr){
  asm volatile("ldmatrix.sync.aligned.m8n8.x2.shared.b16 {%0,%1}, [%2];"
    : "=r"(a[0]),"=r"(a[1]) : "r"(addr)); }
DI void hmma(float* d, const uint32_t* a, const uint32_t* b){
  asm volatile("mma.sync.aligned.m16n8k16.row.col.f32.f16.f16.f32 "
    "{%0,%1,%2,%3}, {%4,%5,%6,%7}, {%8,%9}, {%0,%1,%2,%3};"
    : "+f"(d[0]),"+f"(d[1]),"+f"(d[2]),"+f"(d[3])
    : "r"(a[0]),"r"(a[1]),"r"(a[2]),"r"(a[3]), "r"(b[0]),"r"(b[1])); }

// ---------------- pack weights ----------------
// packed n = (h>>3)*40 + g*8 + (h&7) ; fp16
__global__ void pack_w(const float* __restrict__ Wi, const float* __restrict__ bi,
                       const float* __restrict__ Wfl,const float* __restrict__ bfl,
                       const float* __restrict__ Wfr,const float* __restrict__ bfr,
                       const float* __restrict__ Wo, const float* __restrict__ bo,
                       const float* __restrict__ Wu, const float* __restrict__ bu) {
    const float* Ws[5] = {Wi, Wfl, Wfr, Wo, Wu};
    const float* bs[5] = {bi, bfl, bfr, bo, bu};
    int idx = blockIdx.x * blockDim.x + threadIdx.x;
    if (idx < 640 * GD) {
        int nn = idx / GD, k = idx % GD;
        int hoct = nn / 40, rem = nn % 40, g = rem / 8, h3 = rem % 8;
        int h = hoct * 8 + h3;
        g_Wb[idx] = __float2half(Ws[g][h * GD + k]);
    }
    if (idx < 640) {
        int hoct = idx / 40, rem = idx % 40, g = rem / 8, h3 = rem % 8;
        g_bpk[idx] = bs[g][hoct * 8 + h3];
    }
}

// ---------------- build x part of comb for ALL levels (one launch) ----------------
__global__ void build_x_all(const float* __restrict__ x) {
    size_t idx = (size_t)blockIdx.x * blockDim.x + threadIdx.x;
    if (idx >= RT * 32) return;
    size_t rr = idx >> 5;
    int q = (int)(idx & 31);
    int d = 31 - __clz((int)(rr >> 8) + 1);
    int n = 1 << d;
    int r_in = (int)(rr - ((size_t)256 * (n - 1)));
    int b = r_in >> d, j = r_in & (n - 1);
    float4 v = reinterpret_cast<const float4*>(x)[((size_t)b * NTREE + (n - 1 + j)) * 32 + q];
    __half hb[4];
    hb[0] = __float2half(v.x); hb[1] = __float2half(v.y);
    hb[2] = __float2half(v.z); hb[3] = __float2half(v.w);
    __half* row = g_comb + rr * KW;
    *reinterpret_cast<uint2*>(row + q * 4) = *reinterpret_cast<uint2*>(hb);
    if (d == 9) {   // leaves: zero children-h region cols [128,384)
        uint4 z = make_uint4(0, 0, 0, 0);
        *reinterpret_cast<uint4*>(row + 128 + q * 8) = z;
    }
}

// ---------------- fused GEMM (mma.sync fp16) + LSTM epilogue ----------------
// CTA: 128 rows x 80 packed cols, 256 threads, 8 warps, 3 CTAs/SM (24 warps):
//   warpM = wid>>1 (32 rows), warpN = wid&1 (40 cols = 5 gates x 8 h)
static constexpr uint32_t STAGE_A = 128 * 128;           // 16384
static constexpr uint32_t STAGE   = STAGE_A + 80 * 128;  // 26624
static constexpr int NSTAGE = 2;
static constexpr uint32_t SMEM_BYTES = 2048 + NSTAGE * STAGE; // 55296 (x3 CTA = 166KB)

__global__ void __launch_bounds__(256, 3) gemm_fused(
    int n, int log2n, int parity, int parity_prev, int has_children, int is_root,
    size_t cur_off, size_t par_off)
{
    extern __shared__ char smem[];
    const uint32_t sb = smem_u32(smem);
    const int tid = threadIdx.x, wid = tid >> 5, lane = tid & 31;
    const int blkh = blockIdx.x;              // packed n [blkh*80, +80)
    const int bm   = blockIdx.y * 128;
    const int warpM = wid >> 1, warpN = wid & 1;
    const __half* comb_cur = g_comb + cur_off * KW;

    float* sbias = reinterpret_cast<float*>(smem);
    if (tid < 80) sbias[tid] = g_bpk[blkh * 80 + tid];

    float acc[2][5][4];
    #pragma unroll
    for (int a = 0; a < 2; a++)
      #pragma unroll
      for (int b = 0; b < 5; b++)
        #pragma unroll
        for (int c = 0; c < 4; c++) acc[a][b][c] = 0.f;

    auto load_chunk = [&](int ch) {
        const uint32_t base = sb + 2048 + (uint32_t)(ch & 1) * STAGE;
        const int kk = ch * 64;
        const __half* abase = comb_cur + (size_t)bm * KW + kk;
        #pragma unroll
        for (int l = 0; l < 4; l++) {                  // A: 128 rows x 8 xf4
            int t = tid + l * 256; int row = t >> 3, c = t & 7;
            cp16(base + swz(row * 128 + c * 16),
                 reinterpret_cast<const char*>(abase + (size_t)row * KW) + c * 16);
        }
        const __half* bbase = g_Wb + (size_t)(blkh * 80) * GD + kk;
        #pragma unroll
        for (int l = 0; l < 3; l++) {                  // B: 80 rows x 8 xf4 = 640
            int t = tid + l * 256;
            if (t < 640) {
                int row = t >> 3, c = t & 7;
                cp16(base + STAGE_A + swz(row * 128 + c * 16),
                     reinterpret_cast<const char*>(bbase + (size_t)row * GD) + c * 16);
            }
        }
        asm volatile("cp.async.commit_group;" ::: "memory");
    };

    load_chunk(0);

    // ldmatrix lane addressing
    const int mat = lane >> 3;
    const int lrow = (mat & 1) * 8 + (lane & 7);   // row within 16-row group (x4)
    const int lkb  = (mat >> 1) * 16;              // k-byte half (x4)
    const int a_row0 = warpM * 32 + lrow;
    const int b_row0 = warpN * 40 + lrow;
    const int b2row  = warpN * 40 + 32 + (lane & 7);        // x2: rows 32..39
    const int b2kb   = ((lane >> 3) & 1) * 16;              // x2: k-byte half

    for (int i = 0; i < NCH; i++) {
        asm volatile("cp.async.wait_group 0;" ::: "memory");
        __syncthreads();
        if (i + 1 < NCH) load_chunk(i + 1);
        const uint32_t base = sb + 2048 + (uint32_t)(i & 1) * STAGE;
        #pragma unroll
        for (int kk = 0; kk < 4; kk++) {
            uint32_t bf[5][2];
            {
                uint32_t r[4];
                uint32_t o = (uint32_t)(b_row0 * 128 + kk * 32 + lkb);
                ldsm4(r, base + STAGE_A + swz(o));
                bf[0][0] = r[0]; bf[0][1] = r[2];
                bf[1][0] = r[1]; bf[1][1] = r[3];
                uint32_t o1 = (uint32_t)((b_row0 + 16) * 128 + kk * 32 + lkb);
                ldsm4(r, base + STAGE_A + swz(o1));
                bf[2][0] = r[0]; bf[2][1] = r[2];
                bf[3][0] = r[1]; bf[3][1] = r[3];
                uint32_t o2 = (uint32_t)(b2row * 128 + kk * 32 + b2kb);
                ldsm2(bf[4], base + STAGE_A + swz(o2));
            }
            #pragma unroll
            for (int mi = 0; mi < 2; mi++) {
                uint32_t a[4];
                uint32_t o = (uint32_t)((a_row0 + mi * 16) * 128 + kk * 32 + lkb);
                ldsm4(a, base + swz(o));
                #pragma unroll
                for (int j = 0; j < 5; j++) hmma(acc[mi][j], a, bf[j]);
            }
        }
    }

    // ---- fused epilogue: all 5 gates for (r,h) live in this thread ----
    const float* cprev = g_cst[parity_prev];
    float* cout = g_cst[parity];
    const int nl = warpN * 40;
    #pragma unroll
    for (int mi = 0; mi < 2; mi++) {
        #pragma unroll
        for (int c = 0; c < 4; c++) {
            int r = bm + warpM * 32 + mi * 16 + (lane >> 2) + ((c & 2) ? 8 : 0);
            int hsub = (lane & 3) * 2 + (c & 1);
            int h = (blkh * 2 + warpN) * 8 + hsub;
            float vi  = sigf(acc[mi][0][c] + sbias[nl +  0 + hsub]);
            float vfl = sigf(acc[mi][1][c] + sbias[nl +  8 + hsub]);
            float vfr = sigf(acc[mi][2][c] + sbias[nl + 16 + hsub]);
            float vo  = sigf(acc[mi][3][c] + sbias[nl + 24 + hsub]);
            float vu  = tanhf(acc[mi][4][c] + sbias[nl + 32 + hsub]);
            int b_ = r >> log2n, j_ = r & (n - 1);
            float cl = 0.f, cr = 0.f;
            if (has_children) {
                size_t chL = ((size_t)b_ * (2 * n) + 2 * j_) * HH;
                cl = cprev[chL + h];
                cr = cprev[chL + HH + h];
            }
            float cc = vi * vu + vfl * cl + vfr * cr;
            float hh = vo * tanhf(cc);
            cout[(size_t)r * HH + h] = cc;
            if (is_root) {
                g_root[r * HH + h] = hh;
            } else {
                __half* pc = g_comb + (par_off + (size_t)b_ * (n >> 1) + (j_ >> 1)) * KW
                             + 128 + (j_ & 1) * 128;
                pc[h] = __float2half(hh);
            }
        }
    }
}

// ---------------- final classifier ----------------
__global__ void cls_kernel(const float* __restrict__ Wc, const float* __restrict__ bc,
                           float* __restrict__ out) {
    int idx = blockIdx.x * blockDim.x + threadIdx.x;
    if (idx >= BB * 5) return;
    int b = idx / 5, cc = idx % 5;
    const float* hr = g_root + (size_t)b * HH;
    float s = bc[cc];
    #pragma unroll 4
    for (int h = 0; h < HH; h++) s += hr[h] * Wc[cc * HH + h];
    out[idx] = s;
}

// ---------------- launch ----------------
extern "C" void kernel_launch(void* const* d_in, const int* in_sizes, int n_in,
                              void* d_out, int out_size) {
    (void)in_sizes; (void)n_in; (void)out_size;
    const float* x = (const float*)d_in[0];

    cudaFuncSetAttribute(gemm_fused, cudaFuncAttributeMaxDynamicSharedMemorySize, SMEM_BYTES);

    pack_w<<<(640 * GD + 255) / 256, 256>>>(
        (const float*)d_in[1], (const float*)d_in[2],
        (const float*)d_in[3], (const float*)d_in[4],
        (const float*)d_in[5], (const float*)d_in[6],
        (const float*)d_in[7], (const float*)d_in[8],
        (const float*)d_in[9], (const float*)d_in[10]);

    build_x_all<<<(unsigned)((RT * 32 + 255) / 256), 256>>>(x);

    for (int d = 9; d >= 0; d--) {
        int n = 1 << d;
        int R = BB * n;
        size_t cur_off = (size_t)256 * (n - 1);
        size_t par_off = (d > 0) ? (size_t)256 * ((n >> 1) - 1) : 0;
        dim3 grid(8, R / 128);    // blkh fastest -> A-block L2 reuse across the 8 sharers
        gemm_fused<<<grid, 256, SMEM_BYTES>>>(n, d, d & 1, (d + 1) & 1, d < 9, d == 0,
                                              cur_off, par_off);
    }

    cls_kernel<<<(BB * 5 + 127) / 128, 128>>>(
        (const float*)d_in[11], (const float*)d_in[12], (float*)d_out);
}

// round 11
// speedup vs baseline: 3.1099x; 1.1172x over previous
#include <cuda_runtime.h>
#include <cuda_fp16.h>
#include <cstdint>

#define DI __device__ __forceinline__

static constexpr int BB   = 256;
static constexpr int HH   = 128;
static constexpr int GD   = 384;
static constexpr int NTREE= 1023;
static constexpr int KW   = 384;     // comb row: fp16
static constexpr int NCH  = 6;       // K chunks of 64 per tile
static constexpr size_t RT = (size_t)BB * NTREE;

// ---------------- static device scratch ----------------
__device__ __half g_comb[RT * KW];                    // 201MB, per-level regions
__device__ __half g_Wb[640 * GD];
__device__ float g_bpk[640];
__device__ float g_cst[2][(size_t)BB * 512 * HH];
__device__ float g_root[BB * HH];

// ---------------- helpers ----------------
DI uint32_t smem_u32(const void* p){ uint32_t a;
  asm("{ .reg .u64 t; cvta.to.shared.u64 t, %1; cvt.u32.u64 %0, t; }":"=r"(a):"l"(p)); return a; }
DI uint32_t swz(uint32_t o){ return o ^ ((o >> 3) & 0x70); }
DI void cp16(uint32_t dst, const void* src){
  asm volatile("cp.async.cg.shared.global [%0], [%1], 16;"
               ::"r"(dst),"l"(__cvta_generic_to_global(src)):"memory"); }
DI float sigf(float v){ return 1.f/(1.f+__expf(-v)); }
DI void ldsm4(uint32_t* a, uint32_t addr){
  asm volatile("ldmatrix.sync.aligned.m8n8.x4.shared.b16 {%0,%1,%2,%3}, [%4];"
    : "=r"(a[0]),"=r"(a[1]),"=r"(a[2]),"=r"(a[3]) : "r"(addr)); }
DI void ldsm2(uint32_t* a, uint32_t addr){
  asm volatile("ldmatrix.sync.aligned.m8n8.x2.shared.b16 {%0,%1}, [%2];"
    : "=r"(a[0]),"=r"(a[1]) : "r"(addr)); }
DI void hmma(float* d, const uint32_t* a, const uint32_t* b){
  asm volatile("mma.sync.aligned.m16n8k16.row.col.f32.f16.f16.f32 "
    "{%0,%1,%2,%3}, {%4,%5,%6,%7}, {%8,%9}, {%0,%1,%2,%3};"
    : "+f"(d[0]),"+f"(d[1]),"+f"(d[2]),"+f"(d[3])
    : "r"(a[0]),"r"(a[1]),"r"(a[2]),"r"(a[3]), "r"(b[0]),"r"(b[1])); }

// ---------------- pack weights: packed n = (h>>3)*40 + g*8 + (h&7) ----------------
__global__ void pack_w(const float* __restrict__ Wi, const float* __restrict__ bi,
                       const float* __restrict__ Wfl,const float* __restrict__ bfl,
                       const float* __restrict__ Wfr,const float* __restrict__ bfr,
                       const float* __restrict__ Wo, const float* __restrict__ bo,
                       const float* __restrict__ Wu, const float* __restrict__ bu) {
    const float* Ws[5] = {Wi, Wfl, Wfr, Wo, Wu};
    const float* bs[5] = {bi, bfl, bfr, bo, bu};
    int idx = blockIdx.x * blockDim.x + threadIdx.x;
    if (idx < 640 * GD) {
        int nn = idx / GD, k = idx % GD;
        int hoct = nn / 40, rem = nn % 40, g = rem / 8, h3 = rem % 8;
        g_Wb[idx] = __float2half(Ws[g][(hoct * 8 + h3) * GD + k]);
    }
    if (idx < 640) {
        int hoct = idx / 40, rem = idx % 40, g = rem / 8, h3 = rem % 8;
        g_bpk[idx] = bs[g][hoct * 8 + h3];
    }
}

// ---------------- build x part of comb for ALL levels ----------------
__global__ void build_x_all(const float* __restrict__ x) {
    size_t idx = (size_t)blockIdx.x * blockDim.x + threadIdx.x;
    if (idx >= RT * 32) return;
    size_t rr = idx >> 5;
    int q = (int)(idx & 31);
    int d = 31 - __clz((int)(rr >> 8) + 1);
    int n = 1 << d;
    int r_in = (int)(rr - ((size_t)256 * (n - 1)));
    int b = r_in >> d, j = r_in & (n - 1);
    float4 v = reinterpret_cast<const float4*>(x)[((size_t)b * NTREE + (n - 1 + j)) * 32 + q];
    __half hb[4];
    hb[0] = __float2half(v.x); hb[1] = __float2half(v.y);
    hb[2] = __float2half(v.z); hb[3] = __float2half(v.w);
    __half* row = g_comb + rr * KW;
    *reinterpret_cast<uint2*>(row + q * 4) = *reinterpret_cast<uint2*>(hb);
    if (d == 9) {
        uint4 z = make_uint4(0, 0, 0, 0);
        *reinterpret_cast<uint4*>(row + 128 + q * 8) = z;
    }
}

// ---------------- persistent fused GEMM + LSTM epilogue ----------------
// Tile: 128 rows x 80 packed cols; 256 thr, 8 warps, 3 CTAs/SM.
// Each CTA processes tiles {bid, bid+G, ...}; chunk stream linearized across tiles.
static constexpr uint32_t STAGE_A = 128 * 128;           // 16384
static constexpr uint32_t STAGE   = STAGE_A + 80 * 128;  // 26624
static constexpr uint32_t SMEM_BYTES = 2 * STAGE;        // 53248 (x3 = 160KB/SM)

__global__ void __launch_bounds__(256, 3) gemm_fused(
    int n, int log2n, int parity, int parity_prev, int has_children, int is_root,
    size_t cur_off, size_t par_off, int ntiles, int gstride)
{
    extern __shared__ char smem[];
    const uint32_t sb = smem_u32(smem);
    const int tid = threadIdx.x, wid = tid >> 5, lane = tid & 31;
    const int warpM = wid >> 1, warpN = wid & 1;
    const __half* comb_cur = g_comb + cur_off * KW;

    const int my_nt = (ntiles - (int)blockIdx.x + gstride - 1) / gstride;
    const int Q = my_nt * NCH;

    int lq = 0;   // load cursor (global chunk index)
    auto load_chunk = [&]() {
        if (lq >= Q) return;
        const uint32_t base = sb + (uint32_t)(lq & 1) * STAGE;
        const int lt6 = lq / NCH;
        const int lch = lq - lt6 * NCH;
        const int ltile = (int)blockIdx.x + lt6 * gstride;
        const int bm = (ltile >> 3) * 128, blkh = ltile & 7;
        const int kk = lch * 64;
        const __half* abase = comb_cur + (size_t)bm * KW + kk;
        #pragma unroll
        for (int l = 0; l < 4; l++) {
            int t = tid + l * 256; int row = t >> 3, c = t & 7;
            cp16(base + swz(row * 128 + c * 16),
                 reinterpret_cast<const char*>(abase + (size_t)row * KW) + c * 16);
        }
        const __half* bbase = g_Wb + (size_t)(blkh * 80) * GD + kk;
        #pragma unroll
        for (int l = 0; l < 3; l++) {
            int t = tid + l * 256;
            if (t < 640) {
                int row = t >> 3, c = t & 7;
                cp16(base + STAGE_A + swz(row * 128 + c * 16),
                     reinterpret_cast<const char*>(bbase + (size_t)row * GD) + c * 16);
            }
        }
        asm volatile("cp.async.commit_group;" ::: "memory");
        lq++;
    };

    load_chunk();   // prime

    // ldmatrix lane addressing
    const int mat = lane >> 3;
    const int lrow = (mat & 1) * 8 + (lane & 7);
    const int lkb  = (mat >> 1) * 16;
    const int a_row0 = warpM * 32 + lrow;
    const int b_row0 = warpN * 40 + lrow;
    const int b2row  = warpN * 40 + 32 + (lane & 7);
    const int b2kb   = ((lane >> 3) & 1) * 16;

    const float* cprev = g_cst[parity_prev];
    float* cout = g_cst[parity];

    int cq = 0;   // compute cursor
    for (int k = 0; k < my_nt; k++) {
        float acc[2][5][4];
        #pragma unroll
        for (int a = 0; a < 2; a++)
          #pragma unroll
          for (int b = 0; b < 5; b++)
            #pragma unroll
            for (int c = 0; c < 4; c++) acc[a][b][c] = 0.f;

        #pragma unroll
        for (int i = 0; i < NCH; i++) {
            asm volatile("cp.async.wait_group 0;" ::: "memory");
            __syncthreads();
            load_chunk();
            const uint32_t base = sb + (uint32_t)(cq & 1) * STAGE;
            #pragma unroll
            for (int kk = 0; kk < 4; kk++) {
                uint32_t bf[5][2];
                {
                    uint32_t r[4];
                    uint32_t o = (uint32_t)(b_row0 * 128 + kk * 32 + lkb);
                    ldsm4(r, base + STAGE_A + swz(o));
                    bf[0][0] = r[0]; bf[0][1] = r[2];
                    bf[1][0] = r[1]; bf[1][1] = r[3];
                    uint32_t o1 = (uint32_t)((b_row0 + 16) * 128 + kk * 32 + lkb);
                    ldsm4(r, base + STAGE_A + swz(o1));
                    bf[2][0] = r[0]; bf[2][1] = r[2];
                    bf[3][0] = r[1]; bf[3][1] = r[3];
                    uint32_t o2 = (uint32_t)(b2row * 128 + kk * 32 + b2kb);
                    ldsm2(bf[4], base + STAGE_A + swz(o2));
                }
                #pragma unroll
                for (int mi = 0; mi < 2; mi++) {
                    uint32_t a[4];
                    uint32_t o = (uint32_t)((a_row0 + mi * 16) * 128 + kk * 32 + lkb);
                    ldsm4(a, base + swz(o));
                    #pragma unroll
                    for (int j = 0; j < 5; j++) hmma(acc[mi][j], a, bf[j]);
                }
            }
            cq++;
        }

        // ---- epilogue for this tile (overlaps next tile's in-flight load) ----
        const int tile = (int)blockIdx.x + k * gstride;
        const int bm = (tile >> 3) * 128, blkh = tile & 7;
        const float* bp = g_bpk + blkh * 80 + warpN * 40;
        const int h0 = (blkh * 2 + warpN) * 8 + (lane & 3) * 2;
        #pragma unroll
        for (int mi = 0; mi < 2; mi++) {
            #pragma unroll
            for (int cp = 0; cp < 2; cp++) {
                int r = bm + warpM * 32 + mi * 16 + (lane >> 2) + cp * 8;
                int b_ = r >> log2n, j_ = r & (n - 1);
                float2 clr2 = make_float2(0.f, 0.f), crr2 = make_float2(0.f, 0.f);
                if (has_children) {
                    size_t chL = ((size_t)b_ * (2 * n) + 2 * j_) * HH;
                    clr2 = *reinterpret_cast<const float2*>(cprev + chL + h0);
                    crr2 = *reinterpret_cast<const float2*>(cprev + chL + HH + h0);
                }
                float ccv[2], hhv[2];
                #pragma unroll
                for (int e = 0; e < 2; e++) {
                    int c = cp * 2 + e;
                    int hs = (lane & 3) * 2 + e;
                    float vi  = sigf(acc[mi][0][c] + bp[ 0 + hs]);
                    float vfl = sigf(acc[mi][1][c] + bp[ 8 + hs]);
                    float vfr = sigf(acc[mi][2][c] + bp[16 + hs]);
                    float vo  = sigf(acc[mi][3][c] + bp[24 + hs]);
                    float vu  = tanhf(acc[mi][4][c] + bp[32 + hs]);
                    float cl = e ? clr2.y : clr2.x;
                    float cr = e ? crr2.y : crr2.x;
                    float cc = vi * vu + vfl * cl + vfr * cr;
                    ccv[e] = cc;
                    hhv[e] = vo * tanhf(cc);
                }
                *reinterpret_cast<float2*>(cout + (size_t)r * HH + h0) =
                    make_float2(ccv[0], ccv[1]);
                if (is_root) {
                    *reinterpret_cast<float2*>(g_root + (size_t)r * HH + h0) =
                        make_float2(hhv[0], hhv[1]);
                } else {
                    __half2 hp = __floats2half2_rn(hhv[0], hhv[1]);
                    __half* pc = g_comb + (par_off + (size_t)b_ * (n >> 1) + (j_ >> 1)) * KW
                                 + 128 + (j_ & 1) * 128;
                    *reinterpret_cast<__half2*>(pc + h0) = hp;
                }
            }
        }
    }
}

// ---------------- final classifier ----------------
__global__ void cls_kernel(const float* __restrict__ Wc, const float* __restrict__ bc,
                           float* __restrict__ out) {
    int idx = blockIdx.x * blockDim.x + threadIdx.x;
    if (idx >= BB * 5) return;
    int b = idx / 5, cc = idx % 5;
    const float* hr = g_root + (size_t)b * HH;
    float s = bc[cc];
    #pragma unroll 4
    for (int h = 0; h < HH; h++) s += hr[h] * Wc[cc * HH + h];
    out[idx] = s;
}

// ---------------- launch ----------------
extern "C" void kernel_launch(void* const* d_in, const int* in_sizes, int n_in,
                              void* d_out, int out_size) {
    (void)in_sizes; (void)n_in; (void)out_size;
    const float* x = (const float*)d_in[0];

    cudaFuncSetAttribute(gemm_fused, cudaFuncAttributeMaxDynamicSharedMemorySize, SMEM_BYTES);

    pack_w<<<(640 * GD + 255) / 256, 256>>>(
        (const float*)d_in[1], (const float*)d_in[2],
        (const float*)d_in[3], (const float*)d_in[4],
        (const float*)d_in[5], (const float*)d_in[6],
        (const float*)d_in[7], (const float*)d_in[8],
        (const float*)d_in[9], (const float*)d_in[10]);

    build_x_all<<<(unsigned)((RT * 32 + 255) / 256), 256>>>(x);

    const int MAXG = 456;   // 3 CTAs x 152 SMs
    for (int d = 9; d >= 0; d--) {
        int n = 1 << d;
        int R = BB * n;
        size_t cur_off = (size_t)256 * (n - 1);
        size_t par_off = (d > 0) ? (size_t)256 * ((n >> 1) - 1) : 0;
        int tiles = 8 * (R / 128);
        int grid = tiles < MAXG ? tiles : MAXG;
        gemm_fused<<<grid, 256, SMEM_BYTES>>>(n, d, d & 1, (d + 1) & 1, d < 9, d == 0,
                                              cur_off, par_off, tiles, grid);
    }

    cls_kernel<<<(BB * 5 + 127) / 128, 128>>>(
        (const float*)d_in[11], (const float*)d_in[12], (float*)d_out);
}